// round 1
// baseline (speedup 1.0000x reference)
#include <cuda_runtime.h>
#include <math.h>

#define H_   48
#define W_   48
#define NP   2304        // H_*W_
#define NB   8
#define CIN  128
#define COUT 256
#define NK   9
#define HID  512
#define KC   1152        // NK*CIN
#define VS8  8

// ---------------- scratch (static device globals; no allocation) ----------------
__device__ float  g_xt [NB * NP * CIN];     // x transposed to [b][p][c]   (9.4 MB)
__device__ float  g_wut[KC * COUT];         // Wu transposed to [kc][co]   (1.18 MB)
__device__ float4 g_pk [NP * NK];           // per (p,k): mean_h, mean_w, sigma, pad
__device__ float  g_wts[NB * NP * NK * VS8];
__device__ int    g_lin[NB * NP * NK * VS8];

// ---------------- kernel 0a: transpose x (b,c,p) -> (b,p,c) ----------------
__global__ void transpose_x_kernel(const float* __restrict__ in) {
    __shared__ float tile[32][33];
    int b = blockIdx.z;
    const float* inb = in + (size_t)b * CIN * NP;
    float* outb = g_xt + (size_t)b * NP * CIN;
    int c0 = blockIdx.x * 32;   // p dimension (cols = NP)
    int r0 = blockIdx.y * 32;   // c dimension (rows = CIN)
    int tx = threadIdx.x, ty = threadIdx.y;
#pragma unroll
    for (int q = 0; q < 32; q += 8)
        tile[ty + q][tx] = inb[(r0 + ty + q) * NP + c0 + tx];
    __syncthreads();
#pragma unroll
    for (int q = 0; q < 32; q += 8)
        outb[(size_t)(c0 + ty + q) * CIN + r0 + tx] = tile[tx][ty + q];
}

// ---------------- kernel 0b: transpose Wu (co,kc) -> (kc,co) ----------------
__global__ void transpose_wu_kernel(const float* __restrict__ wu) {
    __shared__ float tile[32][33];
    int c0 = blockIdx.x * 32;   // kc dimension (cols = KC)
    int r0 = blockIdx.y * 32;   // co dimension (rows = COUT)
    int tx = threadIdx.x, ty = threadIdx.y;
#pragma unroll
    for (int q = 0; q < 32; q += 8)
        tile[ty + q][tx] = wu[(size_t)(r0 + ty + q) * KC + c0 + tx];
    __syncthreads();
#pragma unroll
    for (int q = 0; q < 32; q += 8)
        g_wut[(size_t)(c0 + ty + q) * COUT + r0 + tx] = tile[tx][ty + q];
}

// ---------------- kernel 1: per-pixel MLP -> means / sigma ----------------
// Batch-independent: only 2304 pixels.
__global__ void mlp_kernel(const float* __restrict__ W1, const float* __restrict__ b1,
                           const float* __restrict__ W2, const float* __restrict__ b2) {
    __shared__ float hid[HID];
    __shared__ float params[32];
    int p = blockIdx.x;
    int i = p / W_, j = p % W_;
    float ri = (float)i / 47.0f;
    float cj = (float)j / 47.0f;
    int t = threadIdx.x;   // 128 threads
#pragma unroll
    for (int q = 0; q < 4; q++) {
        int n = t + 128 * q;
        float v = W1[2 * n] * ri + W1[2 * n + 1] * cj + b1[n];
        hid[n] = fmaxf(v, 0.0f);
    }
    __syncthreads();
    if (t < 27) {
        float s = b2[t];
        const float* w2r = W2 + (size_t)t * HID;
        for (int n = 0; n < HID; n++) s += hid[n] * w2r[n];
        params[t] = s;
    }
    __syncthreads();
    if (t < NK) {
        int k = t;
        float mrh = params[2 * k];
        float mrw = params[2 * k + 1];
        float sr  = params[18 + k];
        float sch = ri * 0.9999f + 5e-5f;
        float scw = cj * 0.9999f + 5e-5f;
        float midh = logf(sch / (1.0f - sch));
        float midw = logf(scw / (1.0f - scw));
        float mh = 47.0f / (1.0f + expf(-(midh + 0.1f * mrh)));
        float mw = 47.0f / (1.0f + expf(-(midw + 0.1f * mrw)));
        float sp = sr + 2.0f;
        float spl = (sp > 20.0f) ? sp : log1pf(expf(sp));
        float sig = (spl + 0.05f) * (48.0f * 0.05f);   // same for both dims (h==w)
        g_pk[p * NK + k] = make_float4(mh, mw, sig, 0.0f);
    }
}

// ---------------- kernel 2: candidate cells, dedup, normalized weights ----------------
__global__ void weights_kernel(const int* __restrict__ gints, const int* __restrict__ roff) {
    int t = blockIdx.x * 256 + threadIdx.x;         // item = (b, p, k), k fastest
    if (t >= NB * NP * NK) return;
    int k = t % NK;
    int p = (t / NK) % NP;
    float4 pk = g_pk[p * NK + k];
    float mh = pk.x, mw = pk.y, sig = pk.z;
    int flh = (int)floorf(mh);
    int flw = (int)floorf(mw);

    int r[8], c[8];
    r[0] = flh;     c[0] = flw;
    r[1] = flh;     c[1] = flw + 1;
    r[2] = flh + 1; c[2] = flw;
    r[3] = flh + 1; c[3] = flw + 1;
    int4 g  = *(const int4*)(gints + (size_t)t * 4);
    r[4] = g.x;  c[4] = g.y;
    r[5] = g.z;  c[5] = g.w;
    int4 ro = *(const int4*)(roff + (size_t)t * 4);
    r[6] = flh + ro.x - 6; c[6] = flw + ro.y - 6;   // REGION/2 = 6
    r[7] = flh + ro.z - 6; c[7] = flw + ro.w - 6;
#pragma unroll
    for (int v = 0; v < 8; v++) {
        r[v] = (r[v] + 48) % 48;   // all values >= -6, so +48 suffices
        c[v] = (c[v] + 48) % 48;
    }

    float inv_s = 1.0f / sig;
    float pr[8];
    float sum = 0.0f;
#pragma unroll
    for (int v = 0; v < 8; v++) {
        bool dup = false;
#pragma unroll
        for (int u = 0; u < 8; u++)
            if (u < v && r[v] == r[u] && c[v] == c[u]) dup = true;
        float dh = ((float)r[v] - mh) * inv_s;
        float dw = ((float)c[v] - mw) * inv_s;
        float e = dup ? 0.0f : expf(-0.5f * (dh * dh + dw * dw));
        pr[v] = e;
        sum += e;
    }
    float inv = 1.0f / sum;
    float wv[8];
    int   lv[8];
#pragma unroll
    for (int v = 0; v < 8; v++) {
        wv[v] = pr[v] * inv;
        lv[v] = r[v] * 48 + c[v];
    }
    *(float4*)(g_wts + (size_t)t * 8)     = make_float4(wv[0], wv[1], wv[2], wv[3]);
    *(float4*)(g_wts + (size_t)t * 8 + 4) = make_float4(wv[4], wv[5], wv[6], wv[7]);
    *(int4*)(g_lin + (size_t)t * 8)       = make_int4(lv[0], lv[1], lv[2], lv[3]);
    *(int4*)(g_lin + (size_t)t * 8 + 4)   = make_int4(lv[4], lv[5], lv[6], lv[7]);
}

// ---------------- kernel 3: fused gather + GEMM + bias + transpose-store ----------------
// O[m, n] = sum_{kk,c} A[m, kk*128+c] * Wut[kk*128+c, n] + bu[n]
// A built on the fly in smem: A[m][c] = sum_v w[m,kk,v] * xt[b][lin_v][c]
// BM = 64 pixels (one batch each), BN = 256 (full N -> each pixel gathered once).
__global__ void __launch_bounds__(256, 2) gemm_kernel(const float* __restrict__ bu,
                                                      float* __restrict__ out) {
    __shared__ float As[64 * 128];   // 32 KB, layout [px][c]
    __shared__ float Bs[16 * 256];   // 16 KB, layout [c][n]
    int m0  = blockIdx.x * 64;
    int b   = m0 / NP;
    int pb0 = m0 % NP;               // 2304 % 64 == 0 -> tile never crosses batch
    const float* xtb = g_xt + (size_t)b * NP * CIN;
    int tid = threadIdx.x;
    int ng = tid & 31;               // 32 n-groups of 8
    int mg = tid >> 5;               // 8 m-groups of 8
    float acc[8][8];
#pragma unroll
    for (int i = 0; i < 8; i++)
#pragma unroll
        for (int j = 0; j < 8; j++) acc[i][j] = 0.0f;

    int wlbase = (b * NP + pb0) * NK * VS8;

    for (int kk = 0; kk < NK; kk++) {
        __syncthreads();             // prior reads of As complete
        // ---- build As: warp lanes -> consecutive c (coalesced 512B gather rows) ----
#pragma unroll
        for (int it = 0; it < 8; it++) {
            int idx = it * 256 + tid;
            int c4 = idx & 31;       // float4 chunk of channels
            int px = idx >> 5;
            int wb = wlbase + (px * NK + kk) * VS8;
            float4 w0 = *(const float4*)(g_wts + wb);
            float4 w1 = *(const float4*)(g_wts + wb + 4);
            int4   l0 = *(const int4*)(g_lin + wb);
            int4   l1 = *(const int4*)(g_lin + wb + 4);
            float4 a = make_float4(0.f, 0.f, 0.f, 0.f);
#define GATH(WV, LV)                                                            \
            {                                                                   \
                float4 rv = *(const float4*)(xtb + (size_t)(LV) * CIN + c4 * 4);\
                a.x += (WV) * rv.x; a.y += (WV) * rv.y;                         \
                a.z += (WV) * rv.z; a.w += (WV) * rv.w;                         \
            }
            GATH(w0.x, l0.x) GATH(w0.y, l0.y) GATH(w0.z, l0.z) GATH(w0.w, l0.w)
            GATH(w1.x, l1.x) GATH(w1.y, l1.y) GATH(w1.z, l1.z) GATH(w1.w, l1.w)
#undef GATH
            *(float4*)(As + px * 128 + c4 * 4) = a;
        }
        __syncthreads();             // As ready

        const float* wut_kk = g_wut + (size_t)kk * 128 * 256;
        for (int c0 = 0; c0 < 128; c0 += 16) {
            // ---- load Bs chunk [16][256] ----
#pragma unroll
            for (int q = 0; q < 4; q++) {
                int idx = q * 256 + tid;         // 1024 float4 slots
                int n4 = idx & 63;
                int cc = idx >> 6;
                *(float4*)(Bs + cc * 256 + n4 * 4) =
                    *(const float4*)(wut_kk + (size_t)(c0 + cc) * 256 + n4 * 4);
            }
            __syncthreads();         // Bs ready
#pragma unroll
            for (int cc = 0; cc < 16; cc++) {
                float af[8];
#pragma unroll
                for (int i = 0; i < 8; i++)
                    af[i] = As[(mg * 8 + i) * 128 + c0 + cc];   // broadcast
                float4 b0 = *(const float4*)(Bs + cc * 256 + ng * 8);
                float4 b1 = *(const float4*)(Bs + cc * 256 + ng * 8 + 4);
                float bf[8] = {b0.x, b0.y, b0.z, b0.w, b1.x, b1.y, b1.z, b1.w};
#pragma unroll
                for (int i = 0; i < 8; i++)
#pragma unroll
                    for (int j = 0; j < 8; j++)
                        acc[i][j] += af[i] * bf[j];
            }
            __syncthreads();         // done reading Bs before next overwrite
        }
    }

    // ---- epilogue: + bias, store to out[b][co][p] (coalesced float4 along p) ----
    size_t obase = (size_t)b * COUT * NP + pb0 + mg * 8;
#pragma unroll
    for (int j = 0; j < 8; j++) {
        int n = ng * 8 + j;
        float bb = bu[n];
        float4 v0 = make_float4(acc[0][j] + bb, acc[1][j] + bb,
                                acc[2][j] + bb, acc[3][j] + bb);
        float4 v1 = make_float4(acc[4][j] + bb, acc[5][j] + bb,
                                acc[6][j] + bb, acc[7][j] + bb);
        *(float4*)(out + obase + (size_t)n * NP)     = v0;
        *(float4*)(out + obase + (size_t)n * NP + 4) = v1;
    }
}

// ---------------- launch ----------------
extern "C" void kernel_launch(void* const* d_in, const int* in_sizes, int n_in,
                              void* d_out, int out_size) {
    const float* x     = (const float*)d_in[0];
    const float* W1    = (const float*)d_in[1];
    const float* b1    = (const float*)d_in[2];
    const float* W2    = (const float*)d_in[3];
    const float* b2    = (const float*)d_in[4];
    const float* Wu    = (const float*)d_in[5];
    const float* bu    = (const float*)d_in[6];
    const int*   gints = (const int*)d_in[7];
    const int*   roff  = (const int*)d_in[8];
    float* out = (float*)d_out;

    {
        dim3 blk(32, 8);
        dim3 grd(NP / 32, CIN / 32, NB);
        transpose_x_kernel<<<grd, blk>>>(x);
    }
    {
        dim3 blk(32, 8);
        dim3 grd(KC / 32, COUT / 32, 1);
        transpose_wu_kernel<<<grd, blk>>>(Wu);
    }
    mlp_kernel<<<NP, 128>>>(W1, b1, W2, b2);
    {
        int items = NB * NP * NK;                  // 165888
        weights_kernel<<<(items + 255) / 256, 256>>>(gints, roff);
    }
    gemm_kernel<<<(NB * NP) / 64, 256>>>(bu, out);
}

// round 7
// speedup vs baseline: 2.7203x; 2.7203x over previous
#include <cuda_runtime.h>
#include <cuda_bf16.h>
#include <math.h>
#include <stdint.h>

#define H_   48
#define W_   48
#define NP   2304        // H_*W_
#define NB   8
#define CIN  128
#define COUT 256
#define NK   9
#define HID  512
#define KC   1152        // NK*CIN
#define VS8  8

#define MT   128         // M tile (pixels per block)
#define NT   256         // N tile (full cout)
#define KT   128         // K chunk per kk slice

// padded row: 128 bf16 + 8 pad = 136 elems = 272 bytes
#define RP    272
#define A_SZ  (MT * RP)          // 34816 per matrix
#define B_SZ  (NT * RP)          // 69632 per matrix

// ---------------- scratch (static device globals; no allocation) ----------------
__device__ float  g_xt [NB * NP * CIN];               // x transposed to [b][p][c]
__device__ float4 g_pk [NP * NK];                     // mean_h, mean_w, sigma
__device__ float  g_wts[NB * NP * NK * VS8];
__device__ int    g_lin[NB * NP * NK * VS8];
// Wu pre-split bf16 hi/lo per kk: [hi 256*272][lo 256*272] = 139264 B per kk
__device__ unsigned char g_wub[NK * 2 * B_SZ];

// ---------------- helpers ----------------
__device__ __forceinline__ uint32_t smem_u32(const void* p) {
    uint32_t a;
    asm("{ .reg .u64 t; cvta.to.shared.u64 t, %1; cvt.u32.u64 %0, t; }" : "=r"(a) : "l"(p));
    return a;
}

__device__ __forceinline__ void ldm_x4(uint32_t* r, uint32_t addr) {
    asm volatile("ldmatrix.sync.aligned.m8n8.x4.shared.b16 {%0,%1,%2,%3}, [%4];"
                 : "=r"(r[0]), "=r"(r[1]), "=r"(r[2]), "=r"(r[3]) : "r"(addr));
}
__device__ __forceinline__ void mma_bf16(float* d, const uint32_t* a, const uint32_t* b) {
    asm volatile("mma.sync.aligned.m16n8k16.row.col.f32.bf16.bf16.f32 "
                 "{%0,%1,%2,%3}, {%4,%5,%6,%7}, {%8,%9}, {%0,%1,%2,%3};"
                 : "+f"(d[0]), "+f"(d[1]), "+f"(d[2]), "+f"(d[3])
                 : "r"(a[0]), "r"(a[1]), "r"(a[2]), "r"(a[3]), "r"(b[0]), "r"(b[1]));
}

// split float4 into 4 bf16 hi (8B) + 4 bf16 lo (8B)
__device__ __forceinline__ void split4(float4 v, uint2& hi, uint2& lo) {
    __nv_bfloat16 hx = __float2bfloat16_rn(v.x);
    __nv_bfloat16 hy = __float2bfloat16_rn(v.y);
    __nv_bfloat16 hz = __float2bfloat16_rn(v.z);
    __nv_bfloat16 hw = __float2bfloat16_rn(v.w);
    __nv_bfloat16 lx = __float2bfloat16_rn(v.x - __bfloat162float(hx));
    __nv_bfloat16 ly = __float2bfloat16_rn(v.y - __bfloat162float(hy));
    __nv_bfloat16 lz = __float2bfloat16_rn(v.z - __bfloat162float(hz));
    __nv_bfloat16 lw = __float2bfloat16_rn(v.w - __bfloat162float(hw));
    hi.x = ((uint32_t)__bfloat16_as_ushort(hy) << 16) | __bfloat16_as_ushort(hx);
    hi.y = ((uint32_t)__bfloat16_as_ushort(hw) << 16) | __bfloat16_as_ushort(hz);
    lo.x = ((uint32_t)__bfloat16_as_ushort(ly) << 16) | __bfloat16_as_ushort(lx);
    lo.y = ((uint32_t)__bfloat16_as_ushort(lw) << 16) | __bfloat16_as_ushort(lz);
}

// ---------------- kernel 0a: transpose x (b,c,p) -> (b,p,c) ----------------
__global__ void transpose_x_kernel(const float* __restrict__ in) {
    __shared__ float tile[32][33];
    int b = blockIdx.z;
    const float* inb = in + (size_t)b * CIN * NP;
    float* outb = g_xt + (size_t)b * NP * CIN;
    int c0 = blockIdx.x * 32;
    int r0 = blockIdx.y * 32;
    int tx = threadIdx.x, ty = threadIdx.y;
#pragma unroll
    for (int q = 0; q < 32; q += 8)
        tile[ty + q][tx] = inb[(r0 + ty + q) * NP + c0 + tx];
    __syncthreads();
#pragma unroll
    for (int q = 0; q < 32; q += 8)
        outb[(size_t)(c0 + ty + q) * CIN + r0 + tx] = tile[tx][ty + q];
}

// ---------------- kernel 0b: Wu -> bf16 hi/lo, padded [n][k] rows ----------------
__global__ void wu_prep_kernel(const float* __restrict__ wu) {
    int t = blockIdx.x * 256 + threadIdx.x;      // 9*256*32 = 73728
    if (t >= NK * 256 * 32) return;
    int c4 = t & 31;
    int n  = (t >> 5) & 255;
    int kk = t >> 13;
    float4 v = *(const float4*)(wu + (size_t)n * KC + kk * KT + c4 * 4);
    uint2 hi, lo;
    split4(v, hi, lo);
    unsigned char* base = g_wub + (size_t)kk * 2 * B_SZ;
    *(uint2*)(base + n * RP + c4 * 8)        = hi;
    *(uint2*)(base + B_SZ + n * RP + c4 * 8) = lo;
}

// ---------------- kernel 1: per-pixel MLP -> means / sigma ----------------
__global__ void mlp_kernel(const float* __restrict__ W1, const float* __restrict__ b1,
                           const float* __restrict__ W2, const float* __restrict__ b2) {
    __shared__ float hid[HID];
    __shared__ float params[32];
    int p = blockIdx.x;
    int i = p / W_, j = p % W_;
    float ri = (float)i / 47.0f;
    float cj = (float)j / 47.0f;
    int t = threadIdx.x;   // 128 threads
#pragma unroll
    for (int q = 0; q < 4; q++) {
        int n = t + 128 * q;
        float v = W1[2 * n] * ri + W1[2 * n + 1] * cj + b1[n];
        hid[n] = fmaxf(v, 0.0f);
    }
    __syncthreads();
    if (t < 27) {
        float s0 = b2[t], s1 = 0.f, s2 = 0.f, s3 = 0.f;
        const float* w2r = W2 + (size_t)t * HID;
        for (int n = 0; n < HID; n += 4) {
            s0 += hid[n] * w2r[n];
            s1 += hid[n + 1] * w2r[n + 1];
            s2 += hid[n + 2] * w2r[n + 2];
            s3 += hid[n + 3] * w2r[n + 3];
        }
        params[t] = (s0 + s1) + (s2 + s3);
    }
    __syncthreads();
    if (t < NK) {
        int k = t;
        float mrh = params[2 * k];
        float mrw = params[2 * k + 1];
        float sr  = params[18 + k];
        float sch = ri * 0.9999f + 5e-5f;
        float scw = cj * 0.9999f + 5e-5f;
        float midh = logf(sch / (1.0f - sch));
        float midw = logf(scw / (1.0f - scw));
        float mh = 47.0f / (1.0f + expf(-(midh + 0.1f * mrh)));
        float mw = 47.0f / (1.0f + expf(-(midw + 0.1f * mrw)));
        float sp = sr + 2.0f;
        float spl = (sp > 20.0f) ? sp : log1pf(expf(sp));
        float sig = (spl + 0.05f) * (48.0f * 0.05f);
        g_pk[p * NK + k] = make_float4(mh, mw, sig, 0.0f);
    }
}

// ---------------- kernel 2: candidate cells, dedup, normalized weights ----------------
__global__ void weights_kernel(const int* __restrict__ gints, const int* __restrict__ roff) {
    int t = blockIdx.x * 256 + threadIdx.x;
    if (t >= NB * NP * NK) return;
    int k = t % NK;
    int p = (t / NK) % NP;
    float4 pk = g_pk[p * NK + k];
    float mh = pk.x, mw = pk.y, sig = pk.z;
    int flh = (int)floorf(mh);
    int flw = (int)floorf(mw);

    int r[8], c[8];
    r[0] = flh;     c[0] = flw;
    r[1] = flh;     c[1] = flw + 1;
    r[2] = flh + 1; c[2] = flw;
    r[3] = flh + 1; c[3] = flw + 1;
    int4 g  = *(const int4*)(gints + (size_t)t * 4);
    r[4] = g.x;  c[4] = g.y;
    r[5] = g.z;  c[5] = g.w;
    int4 ro = *(const int4*)(roff + (size_t)t * 4);
    r[6] = flh + ro.x - 6; c[6] = flw + ro.y - 6;
    r[7] = flh + ro.z - 6; c[7] = flw + ro.w - 6;
#pragma unroll
    for (int v = 0; v < 8; v++) {
        r[v] = (r[v] + 48) % 48;
        c[v] = (c[v] + 48) % 48;
    }

    float inv_s = 1.0f / sig;
    float pr[8];
    float sum = 0.0f;
#pragma unroll
    for (int v = 0; v < 8; v++) {
        bool dup = false;
#pragma unroll
        for (int u = 0; u < 8; u++)
            if (u < v && r[v] == r[u] && c[v] == c[u]) dup = true;
        float dh = ((float)r[v] - mh) * inv_s;
        float dw = ((float)c[v] - mw) * inv_s;
        float e = dup ? 0.0f : expf(-0.5f * (dh * dh + dw * dw));
        pr[v] = e;
        sum += e;
    }
    float inv = 1.0f / sum;
    float wv[8];
    int   lv[8];
#pragma unroll
    for (int v = 0; v < 8; v++) {
        wv[v] = pr[v] * inv;
        lv[v] = r[v] * 48 + c[v];
    }
    *(float4*)(g_wts + (size_t)t * 8)     = make_float4(wv[0], wv[1], wv[2], wv[3]);
    *(float4*)(g_wts + (size_t)t * 8 + 4) = make_float4(wv[4], wv[5], wv[6], wv[7]);
    *(int4*)(g_lin + (size_t)t * 8)       = make_int4(lv[0], lv[1], lv[2], lv[3]);
    *(int4*)(g_lin + (size_t)t * 8 + 4)   = make_int4(lv[4], lv[5], lv[6], lv[7]);
}

// ---------------- kernel 3: fused gather + mma.sync bf16-split GEMM ----------------
// smem: A_hi[128][136] A_lo B_hi[256][136] B_lo  (bf16, padded rows)
#define SM_AHI 0
#define SM_ALO (SM_AHI + A_SZ)
#define SM_BHI (SM_ALO + A_SZ)
#define SM_BLO (SM_BHI + B_SZ)
#define SM_TOTAL (SM_BLO + B_SZ)

__global__ void __launch_bounds__(512, 1) gemm_mma_kernel(const float* __restrict__ bu,
                                                          float* __restrict__ out) {
    extern __shared__ char smem[];
    uint32_t sb = smem_u32(smem);
    int tid = threadIdx.x;
    int wid = tid >> 5;
    int lid = tid & 31;

    int m0  = blockIdx.x * MT;
    int b   = m0 / NP;
    int p0  = m0 % NP;                 // 2304 % 128 == 0
    const float* xtb = g_xt + (size_t)b * NP * CIN;
    int wlbase = (b * NP + p0) * NK * VS8;

    // warp tiling: 2 warps in M (64 each), 8 in N (32 each)
    int wm = wid & 1;
    int wn = wid >> 1;
    int mbase = wm * 64;
    int nbase = wn * 32;

    // ldmatrix lane address components (all non-trans)
    int a_row = (lid & 15);                         // + mf*16 + mbase
    int a_col = (lid >> 4) * 8;                     // + ks*16
    int b_row = (lid & 7) + ((lid >> 4) & 1) * 8;   // + nf2*16 + nbase
    int b_col = ((lid >> 3) & 1) * 8;               // + ks*16

    float acc[4][4][4];                // [m-frag][n-frag][reg]
#pragma unroll
    for (int i = 0; i < 4; i++)
#pragma unroll
        for (int j = 0; j < 4; j++)
#pragma unroll
            for (int q = 0; q < 4; q++) acc[i][j][q] = 0.0f;

    for (int kk = 0; kk < NK; kk++) {
        // ---- build A_hi/A_lo via weighted gather (4096 slots / 512 thr = 8 iters) ----
#pragma unroll
        for (int it = 0; it < 8; it++) {
            int idx = it * 512 + tid;
            int c4 = idx & 31;
            int px = idx >> 5;
            int wb = wlbase + (px * NK + kk) * VS8;
            float4 w0 = *(const float4*)(g_wts + wb);
            float4 w1 = *(const float4*)(g_wts + wb + 4);
            int4   l0 = *(const int4*)(g_lin + wb);
            int4   l1 = *(const int4*)(g_lin + wb + 4);
            float4 a = make_float4(0.f, 0.f, 0.f, 0.f);
#define GATH(WV, LV)                                                            \
            {                                                                   \
                float4 rv = *(const float4*)(xtb + (size_t)(LV) * CIN + c4 * 4);\
                a.x += (WV) * rv.x; a.y += (WV) * rv.y;                         \
                a.z += (WV) * rv.z; a.w += (WV) * rv.w;                         \
            }
            GATH(w0.x, l0.x) GATH(w0.y, l0.y) GATH(w0.z, l0.z) GATH(w0.w, l0.w)
            GATH(w1.x, l1.x) GATH(w1.y, l1.y) GATH(w1.z, l1.z) GATH(w1.w, l1.w)
#undef GATH
            uint2 hi, lo;
            split4(a, hi, lo);
            *(uint2*)(smem + SM_AHI + px * RP + c4 * 8) = hi;
            *(uint2*)(smem + SM_ALO + px * RP + c4 * 8) = lo;
        }
        // ---- copy B_hi+B_lo (2*B_SZ = 139264 B contiguous, 8704 x 16B) ----
        {
            const uint4* src = (const uint4*)(g_wub + (size_t)kk * 2 * B_SZ);
            uint4* dst = (uint4*)(smem + SM_BHI);
#pragma unroll
            for (int q = 0; q < 17; q++)
                dst[q * 512 + tid] = src[q * 512 + tid];
        }
        __syncthreads();

        // ---- MMA over 8 k-steps ----
#pragma unroll
        for (int ks = 0; ks < 8; ks++) {
            int kc = ks * 16;
            // B fragments: 4 n-frags (2 ldmatrix.x4 each for hi and lo, NON-trans)
            uint32_t bh[8], bl[8];
            {
                uint32_t addr0 = sb + SM_BHI + (nbase + b_row) * RP + (kc + b_col) * 2;
                uint32_t addr1 = sb + SM_BHI + (nbase + 16 + b_row) * RP + (kc + b_col) * 2;
                ldm_x4(bh, addr0);
                ldm_x4(bh + 4, addr1);
                ldm_x4(bl, addr0 + (SM_BLO - SM_BHI));
                ldm_x4(bl + 4, addr1 + (SM_BLO - SM_BHI));
            }
#pragma unroll
            for (int mf = 0; mf < 4; mf++) {
                uint32_t ah[4], al[4];
                uint32_t aaddr = sb + SM_AHI + (mbase + mf * 16 + a_row) * RP + (kc + a_col) * 2;
                ldm_x4(ah, aaddr);
                ldm_x4(al, aaddr + (SM_ALO - SM_AHI));
#pragma unroll
                for (int nf = 0; nf < 4; nf++) {
                    mma_bf16(acc[mf][nf], ah, bh + nf * 2);
                    mma_bf16(acc[mf][nf], ah, bl + nf * 2);
                    mma_bf16(acc[mf][nf], al, bh + nf * 2);
                }
            }
        }
        __syncthreads();   // done reading smem before next kk overwrites
    }

    // ---- epilogue: + bias, store to out[b][co][p] ----
    int grp = lid >> 2;        // 0..7
    int tg  = lid & 3;         // 0..3
    size_t ob = (size_t)b * COUT * NP + p0 + mbase;
#pragma unroll
    for (int nf = 0; nf < 4; nf++) {
        int col0 = nbase + nf * 8 + tg * 2;
        float bb0 = bu[col0];
        float bb1 = bu[col0 + 1];
        size_t o0 = ob + (size_t)col0 * NP;
        size_t o1 = ob + (size_t)(col0 + 1) * NP;
#pragma unroll
        for (int mf = 0; mf < 4; mf++) {
            int rr = mf * 16 + grp;
            out[o0 + rr]     = acc[mf][nf][0] + bb0;
            out[o1 + rr]     = acc[mf][nf][1] + bb1;
            out[o0 + rr + 8] = acc[mf][nf][2] + bb0;
            out[o1 + rr + 8] = acc[mf][nf][3] + bb1;
        }
    }
}

// ---------------- launch ----------------
extern "C" void kernel_launch(void* const* d_in, const int* in_sizes, int n_in,
                              void* d_out, int out_size) {
    const float* x     = (const float*)d_in[0];
    const float* W1    = (const float*)d_in[1];
    const float* b1    = (const float*)d_in[2];
    const float* W2    = (const float*)d_in[3];
    const float* b2    = (const float*)d_in[4];
    const float* Wu    = (const float*)d_in[5];
    const float* bu    = (const float*)d_in[6];
    const int*   gints = (const int*)d_in[7];
    const int*   roff  = (const int*)d_in[8];
    float* out = (float*)d_out;

    {
        dim3 blk(32, 8);
        dim3 grd(NP / 32, CIN / 32, NB);
        transpose_x_kernel<<<grd, blk>>>(x);
    }
    wu_prep_kernel<<<(NK * 256 * 32 + 255) / 256, 256>>>(Wu);
    mlp_kernel<<<NP, 128>>>(W1, b1, W2, b2);
    {
        int items = NB * NP * NK;
        weights_kernel<<<(items + 255) / 256, 256>>>(gints, roff);
    }
    cudaFuncSetAttribute(gemm_mma_kernel, cudaFuncAttributeMaxDynamicSharedMemorySize, SM_TOTAL);
    gemm_mma_kernel<<<(NB * NP) / MT, 512, SM_TOTAL>>>(bu, out);
}

// round 8
// speedup vs baseline: 2.9411x; 1.0812x over previous
#include <cuda_runtime.h>
#include <cuda_bf16.h>
#include <math.h>
#include <stdint.h>

#define H_   48
#define W_   48
#define NP   2304        // H_*W_
#define NB   8
#define CIN  128
#define COUT 256
#define NK   9
#define HID  512
#define KC   1152        // NK*CIN
#define VS8  8

#define MT   128         // M tile (pixels per block)
#define NT   256         // N tile (full cout)
#define KT   128         // K chunk per kk slice

// fp32 row padding: 128 + 4 = 132 floats = 528 bytes (528 mod 128 = 16 -> conflict-free ldmatrix)
#define RPF    132
#define RPF_B  (RPF * 4)         // 528 bytes
#define A_SZ   (MT * RPF_B)      // 67584
#define B_SZ   (NT * RPF_B)      // 135168
#define B_V4   (B_SZ / 16)       // 8448 uint4 per kk slice

// ---------------- scratch (static device globals; no allocation) ----------------
__device__ float  g_xt [NB * NP * CIN];               // x transposed to [b][p][c]
__device__ float4 g_pk [NP * NK];                     // mean_h, mean_w, sigma
__device__ float  g_wts[NB * NP * NK * VS8];
__device__ int    g_lin[NB * NP * NK * VS8];
// Wu as tf32-rounded fp32, padded [n][k] rows per kk slice: 256*132 floats per kk
__device__ float  g_wuf[NK * NT * RPF];

// ---------------- helpers ----------------
__device__ __forceinline__ uint32_t smem_u32(const void* p) {
    uint32_t a;
    asm("{ .reg .u64 t; cvta.to.shared.u64 t, %1; cvt.u32.u64 %0, t; }" : "=r"(a) : "l"(p));
    return a;
}
__device__ __forceinline__ void ldm_x4(uint32_t* r, uint32_t addr) {
    asm volatile("ldmatrix.sync.aligned.m8n8.x4.shared.b16 {%0,%1,%2,%3}, [%4];"
                 : "=r"(r[0]), "=r"(r[1]), "=r"(r[2]), "=r"(r[3]) : "r"(addr));
}
__device__ __forceinline__ void mma_tf32(float* d, const uint32_t* a, const uint32_t* b) {
    asm volatile("mma.sync.aligned.m16n8k8.row.col.f32.tf32.tf32.f32 "
                 "{%0,%1,%2,%3}, {%4,%5,%6,%7}, {%8,%9}, {%0,%1,%2,%3};"
                 : "+f"(d[0]), "+f"(d[1]), "+f"(d[2]), "+f"(d[3])
                 : "r"(a[0]), "r"(a[1]), "r"(a[2]), "r"(a[3]), "r"(b[0]), "r"(b[1]));
}
__device__ __forceinline__ uint32_t f2tf32(float f) {
    uint32_t o;
    asm("cvt.rna.tf32.f32 %0, %1;" : "=r"(o) : "f"(f));
    return o;
}
__device__ __forceinline__ void cp_async16(uint32_t dst, const void* src) {
    asm volatile("cp.async.cg.shared.global [%0], [%1], 16;" :: "r"(dst), "l"(src) : "memory");
}
__device__ __forceinline__ void cp_commit() {
    asm volatile("cp.async.commit_group;" ::: "memory");
}
__device__ __forceinline__ void cp_wait0() {
    asm volatile("cp.async.wait_group 0;" ::: "memory");
}

// ---------------- kernel 0a: transpose x (b,c,p) -> (b,p,c) ----------------
__global__ void transpose_x_kernel(const float* __restrict__ in) {
    __shared__ float tile[32][33];
    int b = blockIdx.z;
    const float* inb = in + (size_t)b * CIN * NP;
    float* outb = g_xt + (size_t)b * NP * CIN;
    int c0 = blockIdx.x * 32;
    int r0 = blockIdx.y * 32;
    int tx = threadIdx.x, ty = threadIdx.y;
#pragma unroll
    for (int q = 0; q < 32; q += 8)
        tile[ty + q][tx] = inb[(r0 + ty + q) * NP + c0 + tx];
    __syncthreads();
#pragma unroll
    for (int q = 0; q < 32; q += 8)
        outb[(size_t)(c0 + ty + q) * CIN + r0 + tx] = tile[tx][ty + q];
}

// ---------------- kernel 0b: Wu -> tf32-rounded fp32, padded [n][k] rows ----------------
__global__ void wu_prep_kernel(const float* __restrict__ wu) {
    int t = blockIdx.x * 256 + threadIdx.x;      // 9*256*32 = 73728
    if (t >= NK * 256 * 32) return;
    int c4 = t & 31;
    int n  = (t >> 5) & 255;
    int kk = t >> 13;
    float4 v = *(const float4*)(wu + (size_t)n * KC + kk * KT + c4 * 4);
    uint4 o;
    o.x = f2tf32(v.x); o.y = f2tf32(v.y); o.z = f2tf32(v.z); o.w = f2tf32(v.w);
    *(uint4*)(g_wuf + (size_t)kk * NT * RPF + n * RPF + c4 * 4) = o;
}

// ---------------- kernel 1: per-pixel MLP -> means / sigma ----------------
__global__ void mlp_kernel(const float* __restrict__ W1, const float* __restrict__ b1,
                           const float* __restrict__ W2, const float* __restrict__ b2) {
    __shared__ float hid[HID];
    __shared__ float params[32];
    int p = blockIdx.x;
    int i = p / W_, j = p % W_;
    float ri = (float)i / 47.0f;
    float cj = (float)j / 47.0f;
    int t = threadIdx.x;   // 128 threads
#pragma unroll
    for (int q = 0; q < 4; q++) {
        int n = t + 128 * q;
        float v = W1[2 * n] * ri + W1[2 * n + 1] * cj + b1[n];
        hid[n] = fmaxf(v, 0.0f);
    }
    __syncthreads();
    if (t < 27) {
        float s0 = b2[t], s1 = 0.f, s2 = 0.f, s3 = 0.f;
        const float* w2r = W2 + (size_t)t * HID;
        for (int n = 0; n < HID; n += 4) {
            s0 += hid[n] * w2r[n];
            s1 += hid[n + 1] * w2r[n + 1];
            s2 += hid[n + 2] * w2r[n + 2];
            s3 += hid[n + 3] * w2r[n + 3];
        }
        params[t] = (s0 + s1) + (s2 + s3);
    }
    __syncthreads();
    if (t < NK) {
        int k = t;
        float mrh = params[2 * k];
        float mrw = params[2 * k + 1];
        float sr  = params[18 + k];
        float sch = ri * 0.9999f + 5e-5f;
        float scw = cj * 0.9999f + 5e-5f;
        float midh = logf(sch / (1.0f - sch));
        float midw = logf(scw / (1.0f - scw));
        float mh = 47.0f / (1.0f + expf(-(midh + 0.1f * mrh)));
        float mw = 47.0f / (1.0f + expf(-(midw + 0.1f * mrw)));
        float sp = sr + 2.0f;
        float spl = (sp > 20.0f) ? sp : log1pf(expf(sp));
        float sig = (spl + 0.05f) * (48.0f * 0.05f);
        g_pk[p * NK + k] = make_float4(mh, mw, sig, 0.0f);
    }
}

// ---------------- kernel 2: candidate cells, dedup, normalized weights ----------------
__global__ void weights_kernel(const int* __restrict__ gints, const int* __restrict__ roff) {
    int t = blockIdx.x * 256 + threadIdx.x;
    if (t >= NB * NP * NK) return;
    int k = t % NK;
    int p = (t / NK) % NP;
    float4 pk = g_pk[p * NK + k];
    float mh = pk.x, mw = pk.y, sig = pk.z;
    int flh = (int)floorf(mh);
    int flw = (int)floorf(mw);

    int r[8], c[8];
    r[0] = flh;     c[0] = flw;
    r[1] = flh;     c[1] = flw + 1;
    r[2] = flh + 1; c[2] = flw;
    r[3] = flh + 1; c[3] = flw + 1;
    int4 g  = *(const int4*)(gints + (size_t)t * 4);
    r[4] = g.x;  c[4] = g.y;
    r[5] = g.z;  c[5] = g.w;
    int4 ro = *(const int4*)(roff + (size_t)t * 4);
    r[6] = flh + ro.x - 6; c[6] = flw + ro.y - 6;
    r[7] = flh + ro.z - 6; c[7] = flw + ro.w - 6;
#pragma unroll
    for (int v = 0; v < 8; v++) {
        r[v] = (r[v] + 48) % 48;
        c[v] = (c[v] + 48) % 48;
    }

    float inv_s = 1.0f / sig;
    float pr[8];
    float sum = 0.0f;
#pragma unroll
    for (int v = 0; v < 8; v++) {
        bool dup = false;
#pragma unroll
        for (int u = 0; u < 8; u++)
            if (u < v && r[v] == r[u] && c[v] == c[u]) dup = true;
        float dh = ((float)r[v] - mh) * inv_s;
        float dw = ((float)c[v] - mw) * inv_s;
        float e = dup ? 0.0f : expf(-0.5f * (dh * dh + dw * dw));
        pr[v] = e;
        sum += e;
    }
    float inv = 1.0f / sum;
    float wv[8];
    int   lv[8];
#pragma unroll
    for (int v = 0; v < 8; v++) {
        wv[v] = pr[v] * inv;
        lv[v] = r[v] * 48 + c[v];
    }
    *(float4*)(g_wts + (size_t)t * 8)     = make_float4(wv[0], wv[1], wv[2], wv[3]);
    *(float4*)(g_wts + (size_t)t * 8 + 4) = make_float4(wv[4], wv[5], wv[6], wv[7]);
    *(int4*)(g_lin + (size_t)t * 8)       = make_int4(lv[0], lv[1], lv[2], lv[3]);
    *(int4*)(g_lin + (size_t)t * 8 + 4)   = make_int4(lv[4], lv[5], lv[6], lv[7]);
}

// ---------------- kernel 3: fused gather + mma.sync tf32 GEMM ----------------
// smem: A[128][132] fp32(tf32), B[256][132] fp32(tf32)
#define SM_A 0
#define SM_B (SM_A + A_SZ)
#define SM_TOTAL (SM_B + B_SZ)

__global__ void __launch_bounds__(512, 1) gemm_mma_kernel(const float* __restrict__ bu,
                                                          float* __restrict__ out) {
    extern __shared__ char smem[];
    uint32_t sb = smem_u32(smem);
    int tid = threadIdx.x;
    int wid = tid >> 5;
    int lid = tid & 31;

    int m0  = blockIdx.x * MT;
    int b   = m0 / NP;
    int p0  = m0 % NP;                 // 2304 % 128 == 0
    const float* xtb = g_xt + (size_t)b * NP * CIN;
    int wlbase = (b * NP + p0) * NK * VS8;

    // warp tiling: 2 warps in M (64 each), 8 in N (32 each)
    int wm = wid & 1;
    int wn = wid >> 1;
    int mbase = wm * 64;
    int nbase = wn * 32;

    // ldmatrix lane address components (tf32 via b16 x4, see analysis)
    int a_row  = (lid & 7) + ((lid >> 3) & 1) * 8;   // + mf*16 + mbase
    int a_ksel = (lid >> 4) * 4;                     // + kc
    int b_row  = (lid & 7) + ((lid >> 4) & 1) * 8;   // + nf2*16 + nbase
    int b_ksel = ((lid >> 3) & 1) * 4;               // + kc

    float acc[4][4][4];                // [m-frag][n-frag][reg]
#pragma unroll
    for (int i = 0; i < 4; i++)
#pragma unroll
        for (int j = 0; j < 4; j++)
#pragma unroll
            for (int q = 0; q < 4; q++) acc[i][j][q] = 0.0f;

    for (int kk = 0; kk < NK; kk++) {
        // ---- issue B copy via cp.async (overlaps with gather below) ----
        {
            const float* src = g_wuf + (size_t)kk * NT * RPF;
#pragma unroll
            for (int q = 0; q < 17; q++) {
                int idx = q * 512 + tid;
                if (idx < B_V4)
                    cp_async16(sb + SM_B + idx * 16, src + idx * 4);
            }
            cp_commit();
        }
        // ---- build A via weighted gather (4096 slots / 512 thr = 8 iters) ----
#pragma unroll
        for (int it = 0; it < 8; it++) {
            int idx = it * 512 + tid;
            int c4 = idx & 31;
            int px = idx >> 5;
            int wb = wlbase + (px * NK + kk) * VS8;
            float4 w0 = *(const float4*)(g_wts + wb);
            float4 w1 = *(const float4*)(g_wts + wb + 4);
            int4   l0 = *(const int4*)(g_lin + wb);
            int4   l1 = *(const int4*)(g_lin + wb + 4);
            float4 a = make_float4(0.f, 0.f, 0.f, 0.f);
#define GATH(WV, LV)                                                            \
            {                                                                   \
                float4 rv = *(const float4*)(xtb + (size_t)(LV) * CIN + c4 * 4);\
                a.x += (WV) * rv.x; a.y += (WV) * rv.y;                         \
                a.z += (WV) * rv.z; a.w += (WV) * rv.w;                         \
            }
            GATH(w0.x, l0.x) GATH(w0.y, l0.y) GATH(w0.z, l0.z) GATH(w0.w, l0.w)
            GATH(w1.x, l1.x) GATH(w1.y, l1.y) GATH(w1.z, l1.z) GATH(w1.w, l1.w)
#undef GATH
            uint4 o;
            o.x = f2tf32(a.x); o.y = f2tf32(a.y); o.z = f2tf32(a.z); o.w = f2tf32(a.w);
            *(uint4*)(smem + SM_A + px * RPF_B + c4 * 16) = o;
        }
        cp_wait0();
        __syncthreads();

        // ---- MMA over 16 k8-steps ----
#pragma unroll
        for (int ks = 0; ks < 16; ks++) {
            int kc = ks * 8;
            // B fragments: 4 n-frags via 2 ldmatrix.x4
            uint32_t bf[8];
            {
                uint32_t addr0 = sb + SM_B + (nbase + b_row) * RPF_B + (kc + b_ksel) * 4;
                uint32_t addr1 = sb + SM_B + (nbase + 16 + b_row) * RPF_B + (kc + b_ksel) * 4;
                ldm_x4(bf, addr0);
                ldm_x4(bf + 4, addr1);
            }
#pragma unroll
            for (int mf = 0; mf < 4; mf++) {
                uint32_t af[4];
                uint32_t aaddr = sb + SM_A + (mbase + mf * 16 + a_row) * RPF_B + (kc + a_ksel) * 4;
                ldm_x4(af, aaddr);
#pragma unroll
                for (int nf = 0; nf < 4; nf++)
                    mma_tf32(acc[mf][nf], af, bf + nf * 2);
            }
        }
        __syncthreads();   // done reading smem before next kk overwrites
    }

    // ---- epilogue: + bias, store to out[b][co][p] ----
    int grp = lid >> 2;        // 0..7
    int tg  = lid & 3;         // 0..3
    size_t ob = (size_t)b * COUT * NP + p0 + mbase;
#pragma unroll
    for (int nf = 0; nf < 4; nf++) {
        int col0 = nbase + nf * 8 + tg * 2;
        float bb0 = bu[col0];
        float bb1 = bu[col0 + 1];
        size_t o0 = ob + (size_t)col0 * NP;
        size_t o1 = ob + (size_t)(col0 + 1) * NP;
#pragma unroll
        for (int mf = 0; mf < 4; mf++) {
            int rr = mf * 16 + grp;
            out[o0 + rr]     = acc[mf][nf][0] + bb0;
            out[o1 + rr]     = acc[mf][nf][1] + bb1;
            out[o0 + rr + 8] = acc[mf][nf][2] + bb0;
            out[o1 + rr + 8] = acc[mf][nf][3] + bb1;
        }
    }
}

// ---------------- launch ----------------
extern "C" void kernel_launch(void* const* d_in, const int* in_sizes, int n_in,
                              void* d_out, int out_size) {
    const float* x     = (const float*)d_in[0];
    const float* W1    = (const float*)d_in[1];
    const float* b1    = (const float*)d_in[2];
    const float* W2    = (const float*)d_in[3];
    const float* b2    = (const float*)d_in[4];
    const float* Wu    = (const float*)d_in[5];
    const float* bu    = (const float*)d_in[6];
    const int*   gints = (const int*)d_in[7];
    const int*   roff  = (const int*)d_in[8];
    float* out = (float*)d_out;

    {
        dim3 blk(32, 8);
        dim3 grd(NP / 32, CIN / 32, NB);
        transpose_x_kernel<<<grd, blk>>>(x);
    }
    wu_prep_kernel<<<(NK * 256 * 32 + 255) / 256, 256>>>(Wu);
    mlp_kernel<<<NP, 128>>>(W1, b1, W2, b2);
    {
        int items = NB * NP * NK;
        weights_kernel<<<(items + 255) / 256, 256>>>(gints, roff);
    }
    cudaFuncSetAttribute(gemm_mma_kernel, cudaFuncAttributeMaxDynamicSharedMemorySize, SM_TOTAL);
    gemm_mma_kernel<<<(NB * NP) / MT, 512, SM_TOTAL>>>(bu, out);
}